// round 12
// baseline (speedup 1.0000x reference)
#include <cuda_runtime.h>
#include <cuda_bf16.h>
#include <stdint.h>
#include <math.h>

// Problem constants
#define T_TOK 8192
#define H_DIM 2048
#define F_DIM 1408
#define E_NUM 8
#define F2    (2 * F_DIM)
#define FH    (F_DIM / 2)          // u32 (bf16 pairs) per act row
#define HH    (H_DIM / 2)          // 1024 pairs per hidden/w1 row
#define W1_PAIRS ((long long)E_NUM * F2 * HH)      // 23,068,672
#define W2_PAIRS ((long long)E_NUM * H_DIM * FH)   // 11,534,336
#define HID_PAIRS ((long long)T_TOK * HH)          // 8,388,608

// Tiling
#define BK       32
#define RSTRIDE  80                // 64B data + 16B pad (16B-aligned rows: 80=5*16)
#define A_BYTES  (128 * RSTRIDE)   // 10240
#define B_BYTES  (256 * RSTRIDE)   // 20480
#define STAGE_B  (2 * A_BYTES + 2 * B_BYTES)   // 61440
#define SMEM_TILES_OFF 1024
#define SMEM_TOTAL (SMEM_TILES_OFF + 3 * STAGE_B)   // 185344

// ---------------------------------------------------------------------------
// Static device scratch
// ---------------------------------------------------------------------------
__device__ int   g_cnt[E_NUM];
__device__ int   g_tok[E_NUM * T_TOK];
__device__ float g_wgt[E_NUM * T_TOK];
__device__ __align__(16) unsigned g_act_hi[(size_t)E_NUM * T_TOK * FH];
__device__ __align__(16) unsigned g_act_lo[(size_t)E_NUM * T_TOK * FH];
__device__ __align__(16) unsigned g_w1_hi[W1_PAIRS];
__device__ __align__(16) unsigned g_w1_lo[W1_PAIRS];
__device__ __align__(16) unsigned g_w2_hi[W2_PAIRS];
__device__ __align__(16) unsigned g_w2_lo[W2_PAIRS];
__device__ __align__(16) unsigned g_hid_hi[HID_PAIRS];
__device__ __align__(16) unsigned g_hid_lo[HID_PAIRS];

// ---------------------------------------------------------------------------
// Helpers
// ---------------------------------------------------------------------------
__device__ __forceinline__ uint32_t smem_u32(const void* p) {
    uint32_t a;
    asm("{ .reg .u64 t; cvta.to.shared.u64 t, %1; cvt.u32.u64 %0, t; }"
        : "=r"(a) : "l"(p));
    return a;
}

__device__ __forceinline__ void ldm4(uint32_t* r, uint32_t addr) {
    asm volatile("ldmatrix.sync.aligned.m8n8.x4.shared.b16 {%0,%1,%2,%3}, [%4];"
                 : "=r"(r[0]), "=r"(r[1]), "=r"(r[2]), "=r"(r[3]) : "r"(addr));
}

__device__ __forceinline__ void mma_bf16(float* c, const uint32_t* a,
                                         uint32_t b0, uint32_t b1) {
    asm volatile(
        "mma.sync.aligned.m16n8k16.row.col.f32.bf16.bf16.f32 "
        "{%0,%1,%2,%3}, {%4,%5,%6,%7}, {%8,%9}, {%0,%1,%2,%3};"
        : "+f"(c[0]), "+f"(c[1]), "+f"(c[2]), "+f"(c[3])
        : "r"(a[0]), "r"(a[1]), "r"(a[2]), "r"(a[3]), "r"(b0), "r"(b1));
}

__device__ __forceinline__ void cpa16(uint32_t saddr, const void* gaddr) {
    asm volatile("cp.async.cg.shared.global [%0], [%1], 16;"
                 :: "r"(saddr), "l"(gaddr) : "memory");
}
#define CP_COMMIT() asm volatile("cp.async.commit_group;" ::: "memory")
#define CP_WAIT1()  asm volatile("cp.async.wait_group 1;" ::: "memory")

// split fp32 -> bf16 hi + bf16 lo (residual); pair packs k-even in low half
__device__ __forceinline__ void split2(float a0, float a1, uint32_t& hi, uint32_t& lo) {
    asm("cvt.rn.satfinite.bf16x2.f32 %0, %1, %2;" : "=r"(hi) : "f"(a1), "f"(a0));
    float h0 = __uint_as_float(hi << 16);
    float h1 = __uint_as_float(hi & 0xFFFF0000u);
    float r0 = a0 - h0;
    float r1 = a1 - h1;
    asm("cvt.rn.satfinite.bf16x2.f32 %0, %1, %2;" : "=r"(lo) : "f"(r1), "f"(r0));
}

// ---------------------------------------------------------------------------
// init / route (proven)
// ---------------------------------------------------------------------------
__global__ void init_kernel(float* __restrict__ out) {
    int idx = blockIdx.x * blockDim.x + threadIdx.x;
    if (idx < E_NUM) g_cnt[idx] = 0;
    const long long n = (long long)T_TOK * H_DIM;
    long long stride = (long long)gridDim.x * blockDim.x;
    for (long long i = idx; i < n; i += stride) out[i] = 0.0f;
}

__global__ void route_kernel(const float* __restrict__ logits) {
    int t = blockIdx.x * blockDim.x + threadIdx.x;
    if (t >= T_TOK) return;
    float l[E_NUM];
#pragma unroll
    for (int i = 0; i < E_NUM; i++) l[i] = logits[t * E_NUM + i];
    int i0 = 0; float v0 = l[0];
#pragma unroll
    for (int i = 1; i < E_NUM; i++) if (l[i] > v0) { v0 = l[i]; i0 = i; }
    int i1 = -1; float v1 = -3.402823466e+38f;
#pragma unroll
    for (int i = 0; i < E_NUM; i++) if (i != i0 && l[i] > v1) { v1 = l[i]; i1 = i; }
    float r  = expf(v1 - v0);
    float w0 = 1.0f / (1.0f + r);
    float w1 = r / (1.0f + r);
    int p0 = atomicAdd(&g_cnt[i0], 1);
    g_tok[i0 * T_TOK + p0] = t; g_wgt[i0 * T_TOK + p0] = w0;
    int p1 = atomicAdd(&g_cnt[i1], 1);
    g_tok[i1 * T_TOK + p1] = t; g_wgt[i1 * T_TOK + p1] = w1;
}

// ---------------------------------------------------------------------------
// Pre-split fp32 tensors into bf16 hi/lo pair arrays (streaming)
// ---------------------------------------------------------------------------
__global__ void split_kernel(const float* __restrict__ src,
                             unsigned* __restrict__ hi, unsigned* __restrict__ lo,
                             long long npairs) {
    long long i = (long long)blockIdx.x * blockDim.x + threadIdx.x;
    long long stride = (long long)gridDim.x * blockDim.x;
    for (; 2 * i < npairs; i += stride) {
        float4 v = *(const float4*)(src + i * 4);
        uint32_t h0, l0, h1, l1;
        split2(v.x, v.y, h0, l0);
        split2(v.z, v.w, h1, l1);
        *(uint2*)(hi + i * 2) = make_uint2(h0, h1);
        *(uint2*)(lo + i * 2) = make_uint2(l0, l1);
    }
}

// ---------------------------------------------------------------------------
// Warp-MMA compute for one K-chunk. Per warp: 64(M) x 64(N), K=32.
// Split-bf16: hh + lh + hl terms, fp32 accum.
// ---------------------------------------------------------------------------
__device__ __forceinline__ void compute_chunk(
    float acc[4][8][4],
    uint32_t aH, uint32_t aL, uint32_t bH, uint32_t bL)
{
#pragma unroll
    for (int ks = 0; ks < 2; ks++) {
        const uint32_t ko = ks * 32;
        uint32_t bh[16], bl[16];
#pragma unroll
        for (int t = 0; t < 4; t++) ldm4(bh + 4 * t, bH + t * 16 * RSTRIDE + ko);
#pragma unroll
        for (int t = 0; t < 4; t++) ldm4(bl + 4 * t, bL + t * 16 * RSTRIDE + ko);
#pragma unroll
        for (int mf = 0; mf < 4; mf++) {
            uint32_t ah4[4], al4[4];
            ldm4(ah4, aH + mf * 16 * RSTRIDE + ko);
            ldm4(al4, aL + mf * 16 * RSTRIDE + ko);
#pragma unroll
            for (int nf = 0; nf < 8; nf++)
                mma_bf16(acc[mf][nf], ah4, bh[2 * nf], bh[2 * nf + 1]);
#pragma unroll
            for (int nf = 0; nf < 8; nf++)
                mma_bf16(acc[mf][nf], al4, bh[2 * nf], bh[2 * nf + 1]);
#pragma unroll
            for (int nf = 0; nf < 8; nf++)
                mma_bf16(acc[mf][nf], ah4, bl[2 * nf], bl[2 * nf + 1]);
        }
    }
}

// Per-thread cp.async issue for one chunk: A 2x(hi,lo) 16B + B 4x(hi,lo) 16B
__device__ __forceinline__ void issue_chunk(
    uint32_t stg, uint32_t a_soff, uint32_t b_soff,
    const unsigned* pah, const unsigned* pal,
    const unsigned* pbh, const unsigned* pbl, int c)
{
    const unsigned* ah = pah + c * 16;
    const unsigned* al = pal + c * 16;
    cpa16(stg + a_soff,           ah);
    cpa16(stg + a_soff + 16,      ah + 4);
    cpa16(stg + A_BYTES + a_soff,      al);
    cpa16(stg + A_BYTES + a_soff + 16, al + 4);
    const unsigned* bh = pbh + c * 16;
    const unsigned* bl = pbl + c * 16;
    const uint32_t sbh = stg + 2 * A_BYTES + b_soff;
    const uint32_t sbl = sbh + B_BYTES;
#pragma unroll
    for (int q = 0; q < 4; q++) cpa16(sbh + q * 16, bh + q * 4);
#pragma unroll
    for (int q = 0; q < 4; q++) cpa16(sbl + q * 16, bl + q * 4);
}

// ---------------------------------------------------------------------------
// GEMM1: [128 gathered tokens] x [128 gate + 128 up cols], K=2048
//   grid = (64, 11, 8), 256 threads (8 warps, 64x64 warp tiles)
// ---------------------------------------------------------------------------
__global__ void gemm1_mma(const float* __restrict__ hidden, const float* __restrict__ w1) {
    const int e   = blockIdx.z;
    const int cnt = g_cnt[e];
    const int m0  = blockIdx.x * 128;
    if (m0 >= cnt) return;
    const int n0t = blockIdx.y * 128;

    extern __shared__ char smem[];
    const uint32_t sbase = smem_u32(smem);
    int* stok = (int*)smem;
    const uint32_t tiles = sbase + SMEM_TILES_OFF;

    const int tid  = threadIdx.x;
    const int lane = tid & 31;
    const int wid  = tid >> 5;
    const int wrow = wid & 1;
    const int wcol = wid >> 1;

    if (tid < 128) {
        int i = m0 + tid;
        stok[tid] = (i < cnt) ? g_tok[e * T_TOK + i] : 0;
    }
    __syncthreads();

    // Loader geometry
    const int arow = tid >> 1;
    const int half = tid & 1;
    const int brow = tid;
    const int bj   = (brow >> 3) & 7;
    const int fcol = n0t + (brow >> 6) * 32 + (bj >> 1) * 8 + (brow & 7);
    const int grow = fcol + ((bj & 1) ? F_DIM : 0);

    const unsigned* pah = g_hid_hi + (size_t)stok[arow] * HH + half * 8;
    const unsigned* pal = g_hid_lo + (size_t)stok[arow] * HH + half * 8;
    const unsigned* pbh = g_w1_hi + (size_t)e * F2 * HH + (size_t)grow * HH;
    const unsigned* pbl = g_w1_lo + (size_t)e * F2 * HH + (size_t)grow * HH;

    const uint32_t a_soff = (uint32_t)(arow * RSTRIDE + half * 32);
    const uint32_t b_soff = (uint32_t)(brow * RSTRIDE);

    const uint32_t a_loff = (uint32_t)((lane & 15) * RSTRIDE + (lane >> 4) * 16)
                          + (uint32_t)(wrow * 64) * RSTRIDE;
    const uint32_t b_loff = (uint32_t)(((lane & 7) + ((lane >> 4) & 1) * 8) * RSTRIDE
                                       + ((lane >> 3) & 1) * 16)
                          + (uint32_t)(wcol * 64) * RSTRIDE;

    float acc[4][8][4];
#pragma unroll
    for (int i = 0; i < 4; i++)
#pragma unroll
        for (int j = 0; j < 8; j++)
#pragma unroll
            for (int q = 0; q < 4; q++) acc[i][j][q] = 0.0f;

    // prologue: stages 0,1
    issue_chunk(tiles,               a_soff, b_soff, pah, pal, pbh, pbl, 0); CP_COMMIT();
    issue_chunk(tiles + STAGE_B,     a_soff, b_soff, pah, pal, pbh, pbl, 1); CP_COMMIT();

    const int NC = H_DIM / BK;   // 64
    for (int c = 0; c < NC; c++) {
        CP_WAIT1();
        __syncthreads();
        if (c + 2 < NC) {
            issue_chunk(tiles + (uint32_t)((c + 2) % 3) * STAGE_B,
                        a_soff, b_soff, pah, pal, pbh, pbl, c + 2);
            CP_COMMIT();
        }
        const uint32_t rb = tiles + (uint32_t)(c % 3) * STAGE_B;
        compute_chunk(acc, rb + a_loff, rb + A_BYTES + a_loff,
                      rb + 2 * A_BYTES + b_loff, rb + 2 * A_BYTES + B_BYTES + b_loff);
    }

    // epilogue: silu(gate)*up -> g_act hi/lo (gate=even nf, up=odd nf)
    const int g   = lane >> 2;
    const int tig = lane & 3;
#pragma unroll
    for (int mf = 0; mf < 4; mf++) {
        const int r0 = wrow * 64 + mf * 16 + g;
        const int r1 = r0 + 8;
#pragma unroll
        for (int p = 0; p < 4; p++) {
            const int ci = ((n0t + wcol * 32 + p * 8) >> 1) + tig;
            if (m0 + r0 < cnt) {
                float g0 = acc[mf][2*p][0],   g1v = acc[mf][2*p][1];
                float u0 = acc[mf][2*p+1][0], u1  = acc[mf][2*p+1][1];
                float a0 = (g0 / (1.0f + expf(-g0))) * u0;
                float a1 = (g1v / (1.0f + expf(-g1v))) * u1;
                uint32_t hi, lo;
                split2(a0, a1, hi, lo);
                size_t idx = (size_t)(e * T_TOK + m0 + r0) * FH + ci;
                g_act_hi[idx] = hi; g_act_lo[idx] = lo;
            }
            if (m0 + r1 < cnt) {
                float g0 = acc[mf][2*p][2],   g1v = acc[mf][2*p][3];
                float u0 = acc[mf][2*p+1][2], u1  = acc[mf][2*p+1][3];
                float a0 = (g0 / (1.0f + expf(-g0))) * u0;
                float a1 = (g1v / (1.0f + expf(-g1v))) * u1;
                uint32_t hi, lo;
                split2(a0, a1, hi, lo);
                size_t idx = (size_t)(e * T_TOK + m0 + r1) * FH + ci;
                g_act_hi[idx] = hi; g_act_lo[idx] = lo;
            }
        }
    }
}

// ---------------------------------------------------------------------------
// GEMM2: [128 slots] x [256 H cols], K=1408; weighted atomic scatter into out
//   grid = (64, 8, 8), 256 threads
// ---------------------------------------------------------------------------
__global__ void gemm2_mma(const float* __restrict__ w2, float* __restrict__ out) {
    const int e   = blockIdx.z;
    const int cnt = g_cnt[e];
    const int m0  = blockIdx.x * 128;
    if (m0 >= cnt) return;
    const int n0  = blockIdx.y * 256;

    extern __shared__ char smem[];
    const uint32_t sbase = smem_u32(smem);
    int* stok = (int*)smem;
    const uint32_t tiles = sbase + SMEM_TILES_OFF;

    const int tid  = threadIdx.x;
    const int lane = tid & 31;
    const int wid  = tid >> 5;
    const int wrow = wid & 1;
    const int wcol = wid >> 1;

    if (tid < 128) {
        int i = m0 + tid;
        stok[tid] = (i < cnt) ? g_tok[e * T_TOK + i] : 0;
    }
    __syncthreads();

    const int arow = tid >> 1;
    const int half = tid & 1;
    const size_t aslot = (size_t)(e * T_TOK + m0 + arow) * FH + half * 8;
    const unsigned* pah = g_act_hi + aslot;
    const unsigned* pal = g_act_lo + aslot;
    const unsigned* pbh = g_w2_hi + (size_t)e * H_DIM * FH + (size_t)(n0 + tid) * FH;
    const unsigned* pbl = g_w2_lo + (size_t)e * H_DIM * FH + (size_t)(n0 + tid) * FH;

    const uint32_t a_soff = (uint32_t)(arow * RSTRIDE + half * 32);
    const uint32_t b_soff = (uint32_t)(tid * RSTRIDE);

    const uint32_t a_loff = (uint32_t)((lane & 15) * RSTRIDE + (lane >> 4) * 16)
                          + (uint32_t)(wrow * 64) * RSTRIDE;
    const uint32_t b_loff = (uint32_t)(((lane & 7) + ((lane >> 4) & 1) * 8) * RSTRIDE
                                       + ((lane >> 3) & 1) * 16)
                          + (uint32_t)(wcol * 64) * RSTRIDE;

    float acc[4][8][4];
#pragma unroll
    for (int i = 0; i < 4; i++)
#pragma unroll
        for (int j = 0; j < 8; j++)
#pragma unroll
            for (int q = 0; q < 4; q++) acc[i][j][q] = 0.0f;

    issue_chunk(tiles,           a_soff, b_soff, pah, pal, pbh, pbl, 0); CP_COMMIT();
    issue_chunk(tiles + STAGE_B, a_soff, b_soff, pah, pal, pbh, pbl, 1); CP_COMMIT();

    const int NC = F_DIM / BK;   // 44
    for (int c = 0; c < NC; c++) {
        CP_WAIT1();
        __syncthreads();
        if (c + 2 < NC) {
            issue_chunk(tiles + (uint32_t)((c + 2) % 3) * STAGE_B,
                        a_soff, b_soff, pah, pal, pbh, pbl, c + 2);
            CP_COMMIT();
        }
        const uint32_t rb = tiles + (uint32_t)(c % 3) * STAGE_B;
        compute_chunk(acc, rb + a_loff, rb + A_BYTES + a_loff,
                      rb + 2 * A_BYTES + b_loff, rb + 2 * A_BYTES + B_BYTES + b_loff);
    }

    // epilogue: out[token] += w * y (exactly 2 atomics per element across grid)
    const int g   = lane >> 2;
    const int tig = lane & 3;
#pragma unroll
    for (int mf = 0; mf < 4; mf++) {
        const int r0 = wrow * 64 + mf * 16 + g;
        const int r1 = r0 + 8;
        const bool v0 = (m0 + r0) < cnt;
        const bool v1 = (m0 + r1) < cnt;
        const float w0 = v0 ? g_wgt[e * T_TOK + m0 + r0] : 0.0f;
        const float w1 = v1 ? g_wgt[e * T_TOK + m0 + r1] : 0.0f;
        float* o0 = out + (size_t)stok[r0] * H_DIM;
        float* o1 = out + (size_t)stok[r1] * H_DIM;
#pragma unroll
        for (int nf = 0; nf < 8; nf++) {
            const int col = n0 + wcol * 64 + nf * 8 + 2 * tig;
            if (v0) {
                atomicAdd(o0 + col,     w0 * acc[mf][nf][0]);
                atomicAdd(o0 + col + 1, w0 * acc[mf][nf][1]);
            }
            if (v1) {
                atomicAdd(o1 + col,     w1 * acc[mf][nf][2]);
                atomicAdd(o1 + col + 1, w1 * acc[mf][nf][3]);
            }
        }
    }
}

// ---------------------------------------------------------------------------
// Launch
// ---------------------------------------------------------------------------
extern "C" void kernel_launch(void* const* d_in, const int* in_sizes, int n_in,
                              void* d_out, int out_size) {
    (void)in_sizes; (void)n_in; (void)out_size;
    const float* hidden = (const float*)d_in[0];
    const float* logits = (const float*)d_in[1];
    const float* w1     = (const float*)d_in[2];
    const float* w2     = (const float*)d_in[3];
    float*       out    = (float*)d_out;

    cudaFuncSetAttribute(gemm1_mma, cudaFuncAttributeMaxDynamicSharedMemorySize, SMEM_TOTAL);
    cudaFuncSetAttribute(gemm2_mma, cudaFuncAttributeMaxDynamicSharedMemorySize, SMEM_TOTAL);

    unsigned *w1h, *w1l, *w2h, *w2l, *hh, *hl;
    cudaGetSymbolAddress((void**)&w1h, g_w1_hi);
    cudaGetSymbolAddress((void**)&w1l, g_w1_lo);
    cudaGetSymbolAddress((void**)&w2h, g_w2_hi);
    cudaGetSymbolAddress((void**)&w2l, g_w2_lo);
    cudaGetSymbolAddress((void**)&hh,  g_hid_hi);
    cudaGetSymbolAddress((void**)&hl,  g_hid_lo);

    init_kernel<<<2048, 256>>>(out);
    route_kernel<<<T_TOK / 256, 256>>>(logits);

    split_kernel<<<8192, 256>>>(hidden, hh,  hl,  HID_PAIRS);
    split_kernel<<<8192, 256>>>(w1,     w1h, w1l, W1_PAIRS);
    split_kernel<<<8192, 256>>>(w2,     w2h, w2l, W2_PAIRS);

    dim3 g1(T_TOK / 128, F_DIM / 128, E_NUM);   // (64, 11, 8)
    gemm1_mma<<<g1, 256, SMEM_TOTAL>>>(hidden, w1);

    dim3 g2(T_TOK / 128, H_DIM / 256, E_NUM);   // (64, 8, 8)
    gemm2_mma<<<g2, 256, SMEM_TOTAL>>>(w2, out);
}

// round 13
// speedup vs baseline: 1.7719x; 1.7719x over previous
#include <cuda_runtime.h>
#include <cuda_fp16.h>
#include <stdint.h>
#include <math.h>

// Problem constants
#define T_TOK 8192
#define H_DIM 2048
#define F_DIM 1408
#define E_NUM 8
#define F2    (2 * F_DIM)
#define FH    (F_DIM / 2)          // u32 (fp16 pairs) per act row

// Tiling
#define BK       32
#define RSTRIDE  80                // smem bytes per row: 32 fp16 (64B) + 16B pad
#define A_BYTES  (128 * RSTRIDE)   // 10240
#define B_BYTES  (256 * RSTRIDE)   // 20480
#define STAGE_B  (A_BYTES + B_BYTES)            // 30720
#define SMEM_TILES_OFF 1024
#define SMEM_TOTAL (SMEM_TILES_OFF + 3 * STAGE_B)   // 93184

// ---------------------------------------------------------------------------
// Static device scratch
// ---------------------------------------------------------------------------
__device__ int   g_cnt[E_NUM];
__device__ int   g_tok[E_NUM * T_TOK];
__device__ float g_wgt[E_NUM * T_TOK];
__device__ __align__(16) unsigned g_act[(size_t)E_NUM * T_TOK * FH];  // fp16x2

// ---------------------------------------------------------------------------
// Helpers
// ---------------------------------------------------------------------------
__device__ __forceinline__ uint32_t smem_u32(const void* p) {
    uint32_t a;
    asm("{ .reg .u64 t; cvta.to.shared.u64 t, %1; cvt.u32.u64 %0, t; }"
        : "=r"(a) : "l"(p));
    return a;
}

__device__ __forceinline__ void ldm4(uint32_t* r, uint32_t addr) {
    asm volatile("ldmatrix.sync.aligned.m8n8.x4.shared.b16 {%0,%1,%2,%3}, [%4];"
                 : "=r"(r[0]), "=r"(r[1]), "=r"(r[2]), "=r"(r[3]) : "r"(addr));
}

__device__ __forceinline__ void mma_f16(float* c, const uint32_t* a,
                                        uint32_t b0, uint32_t b1) {
    asm volatile(
        "mma.sync.aligned.m16n8k16.row.col.f32.f16.f16.f32 "
        "{%0,%1,%2,%3}, {%4,%5,%6,%7}, {%8,%9}, {%0,%1,%2,%3};"
        : "+f"(c[0]), "+f"(c[1]), "+f"(c[2]), "+f"(c[3])
        : "r"(a[0]), "r"(a[1]), "r"(a[2]), "r"(a[3]), "r"(b0), "r"(b1));
}

__device__ __forceinline__ void sts128(uint32_t addr, uint32_t r0, uint32_t r1,
                                       uint32_t r2, uint32_t r3) {
    asm volatile("st.shared.v4.b32 [%0], {%1, %2, %3, %4};"
                 :: "r"(addr), "r"(r0), "r"(r1), "r"(r2), "r"(r3) : "memory");
}

// pack two fp32 -> fp16x2 (a0 in low half = even k)
__device__ __forceinline__ uint32_t f16pair(float a0, float a1) {
    uint32_t r;
    asm("cvt.rn.f16x2.f32 %0, %1, %2;" : "=r"(r) : "f"(a1), "f"(a0));
    return r;
}

// ---------------------------------------------------------------------------
// init / route (proven)
// ---------------------------------------------------------------------------
__global__ void init_kernel(float* __restrict__ out) {
    int idx = blockIdx.x * blockDim.x + threadIdx.x;
    if (idx < E_NUM) g_cnt[idx] = 0;
    const long long n = (long long)T_TOK * H_DIM;
    long long stride = (long long)gridDim.x * blockDim.x;
    for (long long i = idx; i < n; i += stride) out[i] = 0.0f;
}

__global__ void route_kernel(const float* __restrict__ logits) {
    int t = blockIdx.x * blockDim.x + threadIdx.x;
    if (t >= T_TOK) return;
    float l[E_NUM];
#pragma unroll
    for (int i = 0; i < E_NUM; i++) l[i] = logits[t * E_NUM + i];
    int i0 = 0; float v0 = l[0];
#pragma unroll
    for (int i = 1; i < E_NUM; i++) if (l[i] > v0) { v0 = l[i]; i0 = i; }
    int i1 = -1; float v1 = -3.402823466e+38f;
#pragma unroll
    for (int i = 0; i < E_NUM; i++) if (i != i0 && l[i] > v1) { v1 = l[i]; i1 = i; }
    float r  = expf(v1 - v0);
    float w0 = 1.0f / (1.0f + r);
    float w1 = r / (1.0f + r);
    int p0 = atomicAdd(&g_cnt[i0], 1);
    g_tok[i0 * T_TOK + p0] = t; g_wgt[i0 * T_TOK + p0] = w0;
    int p1 = atomicAdd(&g_cnt[i1], 1);
    g_tok[i1 * T_TOK + p1] = t; g_wgt[i1 * T_TOK + p1] = w1;
}

// ---------------------------------------------------------------------------
// Warp-MMA compute for one K-chunk. Per warp: 64(M) x 64(N), K=32, fp16 single.
// ---------------------------------------------------------------------------
__device__ __forceinline__ void compute_chunk(
    float acc[4][8][4], uint32_t aB, uint32_t bB)
{
#pragma unroll
    for (int ks = 0; ks < 2; ks++) {
        const uint32_t ko = ks * 32;
        uint32_t b[16];
#pragma unroll
        for (int t = 0; t < 4; t++) ldm4(b + 4 * t, bB + t * 16 * RSTRIDE + ko);
#pragma unroll
        for (int mf = 0; mf < 4; mf++) {
            uint32_t a4[4];
            ldm4(a4, aB + mf * 16 * RSTRIDE + ko);
#pragma unroll
            for (int nf = 0; nf < 8; nf++)
                mma_f16(acc[mf][nf], a4, b[2 * nf], b[2 * nf + 1]);
        }
    }
}

// ---------------------------------------------------------------------------
// GEMM1: [128 gathered tokens] x [128 gate + 128 up cols], K=2048
//   grid = (64, 11, 8), 256 threads (8 warps, 64x64 warp tiles)
// ---------------------------------------------------------------------------
__device__ __forceinline__ void g1_load(const float* ap, const float* bp, int k0,
                                        float4* A, float4* B) {
#pragma unroll
    for (int i = 0; i < 4; i++) A[i] = *(const float4*)(ap + k0 + i * 4);
#pragma unroll
    for (int i = 0; i < 8; i++) B[i] = *(const float4*)(bp + k0 + i * 4);
}

__device__ __forceinline__ void g1_sts(uint32_t s, uint32_t a_srow, uint32_t b_srow,
                                       const float4* A, const float4* B) {
    sts128(s + a_srow,
           f16pair(A[0].x, A[0].y), f16pair(A[0].z, A[0].w),
           f16pair(A[1].x, A[1].y), f16pair(A[1].z, A[1].w));
    sts128(s + a_srow + 16,
           f16pair(A[2].x, A[2].y), f16pair(A[2].z, A[2].w),
           f16pair(A[3].x, A[3].y), f16pair(A[3].z, A[3].w));
    const uint32_t bb = s + A_BYTES;
#pragma unroll
    for (int q = 0; q < 4; q++) {
        sts128(bb + b_srow + q * 16,
               f16pair(B[2*q].x, B[2*q].y),     f16pair(B[2*q].z, B[2*q].w),
               f16pair(B[2*q+1].x, B[2*q+1].y), f16pair(B[2*q+1].z, B[2*q+1].w));
    }
}

__global__ void gemm1_mma(const float* __restrict__ hidden, const float* __restrict__ w1) {
    const int e   = blockIdx.z;
    const int cnt = g_cnt[e];
    const int m0  = blockIdx.x * 128;
    if (m0 >= cnt) return;
    const int n0t = blockIdx.y * 128;

    extern __shared__ char smem[];
    const uint32_t sbase = smem_u32(smem);
    int* stok = (int*)smem;
    const uint32_t tiles = sbase + SMEM_TILES_OFF;

    const int tid  = threadIdx.x;
    const int lane = tid & 31;
    const int wid  = tid >> 5;
    const int wrow = wid & 1;
    const int wcol = wid >> 1;

    if (tid < 128) {
        int i = m0 + tid;
        stok[tid] = (i < cnt) ? g_tok[e * T_TOK + i] : 0;
    }
    __syncthreads();

    // Loader geometry
    const int arow = tid >> 1;
    const int akq  = (tid & 1) * 16;
    const int brow = tid;
    const int bj   = (brow >> 3) & 7;
    const int fcol = n0t + (brow >> 6) * 32 + (bj >> 1) * 8 + (brow & 7);
    const int grow = fcol + ((bj & 1) ? F_DIM : 0);

    const float* w1e = w1 + (size_t)e * F2 * H_DIM;
    const float* ap  = hidden + (size_t)stok[arow] * H_DIM + akq;
    const float* bp  = w1e + (size_t)grow * H_DIM;

    const uint32_t a_srow = (uint32_t)(arow * RSTRIDE + akq * 2);
    const uint32_t b_srow = (uint32_t)(brow * RSTRIDE);

    const uint32_t a_loff = (uint32_t)((lane & 15) * RSTRIDE + (lane >> 4) * 16)
                          + (uint32_t)(wrow * 64) * RSTRIDE;
    const uint32_t b_loff = (uint32_t)(((lane & 7) + ((lane >> 4) & 1) * 8) * RSTRIDE
                                       + ((lane >> 3) & 1) * 16)
                          + (uint32_t)(wcol * 64) * RSTRIDE;

    float acc[4][8][4];
#pragma unroll
    for (int i = 0; i < 4; i++)
#pragma unroll
        for (int j = 0; j < 8; j++)
#pragma unroll
            for (int q = 0; q < 4; q++) acc[i][j][q] = 0.0f;

    float4 Ar[4], Br[8];
    g1_load(ap, bp, 0, Ar, Br);
    g1_sts(tiles, a_srow, b_srow, Ar, Br);
    g1_load(ap, bp, BK, Ar, Br);
    __syncthreads();

    const int NC = H_DIM / BK;   // 64
    for (int c = 0; c < NC; c++) {
        const uint32_t rb = tiles + (uint32_t)(c % 3) * STAGE_B;
        if (c + 1 < NC) {
            const uint32_t wb = tiles + (uint32_t)((c + 1) % 3) * STAGE_B;
            g1_sts(wb, a_srow, b_srow, Ar, Br);
        }
        if (c + 2 < NC) g1_load(ap, bp, (c + 2) * BK, Ar, Br);
        compute_chunk(acc, rb + a_loff, rb + A_BYTES + b_loff);
        __syncthreads();
    }

    // epilogue: silu(gate)*up -> g_act fp16 pairs (gate=even nf, up=odd nf)
    const int g   = lane >> 2;
    const int tig = lane & 3;
#pragma unroll
    for (int mf = 0; mf < 4; mf++) {
        const int r0 = wrow * 64 + mf * 16 + g;
        const int r1 = r0 + 8;
#pragma unroll
        for (int p = 0; p < 4; p++) {
            const int ci = ((n0t + wcol * 32 + p * 8) >> 1) + tig;
            if (m0 + r0 < cnt) {
                float g0 = acc[mf][2*p][0],   g1v = acc[mf][2*p][1];
                float u0 = acc[mf][2*p+1][0], u1  = acc[mf][2*p+1][1];
                float a0 = (g0 / (1.0f + expf(-g0))) * u0;
                float a1 = (g1v / (1.0f + expf(-g1v))) * u1;
                g_act[(size_t)(e * T_TOK + m0 + r0) * FH + ci] = f16pair(a0, a1);
            }
            if (m0 + r1 < cnt) {
                float g0 = acc[mf][2*p][2],   g1v = acc[mf][2*p][3];
                float u0 = acc[mf][2*p+1][2], u1  = acc[mf][2*p+1][3];
                float a0 = (g0 / (1.0f + expf(-g0))) * u0;
                float a1 = (g1v / (1.0f + expf(-g1v))) * u1;
                g_act[(size_t)(e * T_TOK + m0 + r1) * FH + ci] = f16pair(a0, a1);
            }
        }
    }
}

// ---------------------------------------------------------------------------
// GEMM2: [128 slots] x [256 H cols], K=1408; weighted atomic scatter into out
//   grid = (64, 8, 8), 256 threads
// ---------------------------------------------------------------------------
__device__ __forceinline__ void g2_load(const unsigned* pa, const float* bp, int c,
                                        uint4* AH, float4* B) {
    AH[0] = *(const uint4*)(pa + c * 16);
    AH[1] = *(const uint4*)(pa + c * 16 + 4);
#pragma unroll
    for (int i = 0; i < 8; i++) B[i] = *(const float4*)(bp + c * BK + i * 4);
}

__device__ __forceinline__ void g2_sts(uint32_t s, uint32_t a_srow, uint32_t b_srow,
                                       const uint4* AH, const float4* B) {
    sts128(s + a_srow,      AH[0].x, AH[0].y, AH[0].z, AH[0].w);
    sts128(s + a_srow + 16, AH[1].x, AH[1].y, AH[1].z, AH[1].w);
    const uint32_t bb = s + A_BYTES;
#pragma unroll
    for (int q = 0; q < 4; q++) {
        sts128(bb + b_srow + q * 16,
               f16pair(B[2*q].x, B[2*q].y),     f16pair(B[2*q].z, B[2*q].w),
               f16pair(B[2*q+1].x, B[2*q+1].y), f16pair(B[2*q+1].z, B[2*q+1].w));
    }
}

__global__ void gemm2_mma(const float* __restrict__ w2, float* __restrict__ out) {
    const int e   = blockIdx.z;
    const int cnt = g_cnt[e];
    const int m0  = blockIdx.x * 128;
    if (m0 >= cnt) return;
    const int n0  = blockIdx.y * 256;

    extern __shared__ char smem[];
    const uint32_t sbase = smem_u32(smem);
    int* stok = (int*)smem;
    const uint32_t tiles = sbase + SMEM_TILES_OFF;

    const int tid  = threadIdx.x;
    const int lane = tid & 31;
    const int wid  = tid >> 5;
    const int wrow = wid & 1;
    const int wcol = wid >> 1;

    if (tid < 128) {
        int i = m0 + tid;
        stok[tid] = (i < cnt) ? g_tok[e * T_TOK + i] : 0;
    }
    __syncthreads();

    const int arow = tid >> 1;
    const int half = tid & 1;
    const unsigned* pa = g_act + (size_t)(e * T_TOK + m0 + arow) * FH + half * 8;
    const float* w2e = w2 + (size_t)e * H_DIM * F_DIM;
    const float* bp  = w2e + (size_t)(n0 + tid) * F_DIM;

    const uint32_t a_srow = (uint32_t)(arow * RSTRIDE + half * 32);
    const uint32_t b_srow = (uint32_t)(tid * RSTRIDE);

    const uint32_t a_loff = (uint32_t)((lane & 15) * RSTRIDE + (lane >> 4) * 16)
                          + (uint32_t)(wrow * 64) * RSTRIDE;
    const uint32_t b_loff = (uint32_t)(((lane & 7) + ((lane >> 4) & 1) * 8) * RSTRIDE
                                       + ((lane >> 3) & 1) * 16)
                          + (uint32_t)(wcol * 64) * RSTRIDE;

    float acc[4][8][4];
#pragma unroll
    for (int i = 0; i < 4; i++)
#pragma unroll
        for (int j = 0; j < 8; j++)
#pragma unroll
            for (int q = 0; q < 4; q++) acc[i][j][q] = 0.0f;

    uint4 AH[2];
    float4 Br[8];
    g2_load(pa, bp, 0, AH, Br);
    g2_sts(tiles, a_srow, b_srow, AH, Br);
    g2_load(pa, bp, 1, AH, Br);
    __syncthreads();

    const int NC = F_DIM / BK;   // 44
    for (int c = 0; c < NC; c++) {
        const uint32_t rb = tiles + (uint32_t)(c % 3) * STAGE_B;
        if (c + 1 < NC) {
            const uint32_t wb = tiles + (uint32_t)((c + 1) % 3) * STAGE_B;
            g2_sts(wb, a_srow, b_srow, AH, Br);
        }
        if (c + 2 < NC) g2_load(pa, bp, c + 2, AH, Br);
        compute_chunk(acc, rb + a_loff, rb + A_BYTES + b_loff);
        __syncthreads();
    }

    // epilogue: out[token] += w * y (exactly 2 atomics per element across grid)
    const int g   = lane >> 2;
    const int tig = lane & 3;
#pragma unroll
    for (int mf = 0; mf < 4; mf++) {
        const int r0 = wrow * 64 + mf * 16 + g;
        const int r1 = r0 + 8;
        const bool v0 = (m0 + r0) < cnt;
        const bool v1 = (m0 + r1) < cnt;
        const float w0 = v0 ? g_wgt[e * T_TOK + m0 + r0] : 0.0f;
        const float w1 = v1 ? g_wgt[e * T_TOK + m0 + r1] : 0.0f;
        float* o0 = out + (size_t)stok[r0] * H_DIM;
        float* o1 = out + (size_t)stok[r1] * H_DIM;
#pragma unroll
        for (int nf = 0; nf < 8; nf++) {
            const int col = n0 + wcol * 64 + nf * 8 + 2 * tig;
            if (v0) {
                atomicAdd(o0 + col,     w0 * acc[mf][nf][0]);
                atomicAdd(o0 + col + 1, w0 * acc[mf][nf][1]);
            }
            if (v1) {
                atomicAdd(o1 + col,     w1 * acc[mf][nf][2]);
                atomicAdd(o1 + col + 1, w1 * acc[mf][nf][3]);
            }
        }
    }
}

// ---------------------------------------------------------------------------
// Launch
// ---------------------------------------------------------------------------
extern "C" void kernel_launch(void* const* d_in, const int* in_sizes, int n_in,
                              void* d_out, int out_size) {
    (void)in_sizes; (void)n_in; (void)out_size;
    const float* hidden = (const float*)d_in[0];
    const float* logits = (const float*)d_in[1];
    const float* w1     = (const float*)d_in[2];
    const float* w2     = (const float*)d_in[3];
    float*       out    = (float*)d_out;

    cudaFuncSetAttribute(gemm1_mma, cudaFuncAttributeMaxDynamicSharedMemorySize, SMEM_TOTAL);
    cudaFuncSetAttribute(gemm2_mma, cudaFuncAttributeMaxDynamicSharedMemorySize, SMEM_TOTAL);

    init_kernel<<<2048, 256>>>(out);
    route_kernel<<<T_TOK / 256, 256>>>(logits);

    dim3 g1(T_TOK / 128, F_DIM / 128, E_NUM);   // (64, 11, 8)
    gemm1_mma<<<g1, 256, SMEM_TOTAL>>>(hidden, w1);

    dim3 g2(T_TOK / 128, H_DIM / 256, E_NUM);   // (64, 8, 8)
    gemm2_mma<<<g2, 256, SMEM_TOTAL>>>(w2, out);
}

// round 14
// speedup vs baseline: 2.4797x; 1.3994x over previous
#include <cuda_runtime.h>
#include <cuda_fp16.h>
#include <stdint.h>
#include <math.h>

// Problem constants
#define T_TOK 8192
#define H_DIM 2048
#define F_DIM 1408
#define E_NUM 8
#define F2    (2 * F_DIM)
#define FH    (F_DIM / 2)          // u32 (fp16 pairs) per F-major row
#define HH    (H_DIM / 2)          // u32 pairs per H-major row
#define HID_PAIRS ((long long)T_TOK * HH)
#define W1_PAIRS  ((long long)E_NUM * F2 * HH)
#define W2_PAIRS  ((long long)E_NUM * H_DIM * FH)

// Tiling
#define BK       32
#define RSTRIDE  80                // smem bytes/row: 32 fp16 (64B) + 16B pad
#define A_BYTES  (128 * RSTRIDE)   // 10240
#define B_BYTES  (256 * RSTRIDE)   // 20480
#define STAGE_B  (A_BYTES + B_BYTES)            // 30720
#define SMEM_TILES_OFF 1024
#define SMEM_TOTAL (SMEM_TILES_OFF + 3 * STAGE_B)   // 93184
#define NTHREADS 320               // 8 consumer warps + 2 producer warps

// ---------------------------------------------------------------------------
// Static device scratch
// ---------------------------------------------------------------------------
__device__ int   g_cnt[E_NUM];
__device__ int   g_tok[E_NUM * T_TOK];
__device__ float g_wgt[E_NUM * T_TOK];
__device__ __align__(16) unsigned g_act[(size_t)E_NUM * T_TOK * FH];   // fp16x2
__device__ __align__(16) unsigned g_hid16[HID_PAIRS];
__device__ __align__(16) unsigned g_w1_16[W1_PAIRS];
__device__ __align__(16) unsigned g_w2_16[W2_PAIRS];

// ---------------------------------------------------------------------------
// Helpers
// ---------------------------------------------------------------------------
__device__ __forceinline__ uint32_t smem_u32(const void* p) {
    uint32_t a;
    asm("{ .reg .u64 t; cvta.to.shared.u64 t, %1; cvt.u32.u64 %0, t; }"
        : "=r"(a) : "l"(p));
    return a;
}

__device__ __forceinline__ void ldm4(uint32_t* r, uint32_t addr) {
    asm volatile("ldmatrix.sync.aligned.m8n8.x4.shared.b16 {%0,%1,%2,%3}, [%4];"
                 : "=r"(r[0]), "=r"(r[1]), "=r"(r[2]), "=r"(r[3]) : "r"(addr));
}

__device__ __forceinline__ void mma_f16(float* c, const uint32_t* a,
                                        uint32_t b0, uint32_t b1) {
    asm volatile(
        "mma.sync.aligned.m16n8k16.row.col.f32.f16.f16.f32 "
        "{%0,%1,%2,%3}, {%4,%5,%6,%7}, {%8,%9}, {%0,%1,%2,%3};"
        : "+f"(c[0]), "+f"(c[1]), "+f"(c[2]), "+f"(c[3])
        : "r"(a[0]), "r"(a[1]), "r"(a[2]), "r"(a[3]), "r"(b0), "r"(b1));
}

__device__ __forceinline__ void cpa16(uint32_t saddr, const unsigned* gaddr) {
    asm volatile("cp.async.cg.shared.global [%0], [%1], 16;"
                 :: "r"(saddr), "l"(gaddr) : "memory");
}
#define CP_COMMIT() asm volatile("cp.async.commit_group;" ::: "memory")
#define CP_WAIT1()  asm volatile("cp.async.wait_group 1;" ::: "memory")

// pack two fp32 -> fp16x2 (a0 in low half = even k)
__device__ __forceinline__ uint32_t f16pair(float a0, float a1) {
    uint32_t r;
    asm("cvt.rn.f16x2.f32 %0, %1, %2;" : "=r"(r) : "f"(a1), "f"(a0));
    return r;
}

// ---------------------------------------------------------------------------
// init / route (proven)
// ---------------------------------------------------------------------------
__global__ void init_kernel(float* __restrict__ out) {
    int idx = blockIdx.x * blockDim.x + threadIdx.x;
    if (idx < E_NUM) g_cnt[idx] = 0;
    const long long n = (long long)T_TOK * H_DIM;
    long long stride = (long long)gridDim.x * blockDim.x;
    for (long long i = idx; i < n; i += stride) out[i] = 0.0f;
}

__global__ void route_kernel(const float* __restrict__ logits) {
    int t = blockIdx.x * blockDim.x + threadIdx.x;
    if (t >= T_TOK) return;
    float l[E_NUM];
#pragma unroll
    for (int i = 0; i < E_NUM; i++) l[i] = logits[t * E_NUM + i];
    int i0 = 0; float v0 = l[0];
#pragma unroll
    for (int i = 1; i < E_NUM; i++) if (l[i] > v0) { v0 = l[i]; i0 = i; }
    int i1 = -1; float v1 = -3.402823466e+38f;
#pragma unroll
    for (int i = 0; i < E_NUM; i++) if (i != i0 && l[i] > v1) { v1 = l[i]; i1 = i; }
    float r  = expf(v1 - v0);
    float w0 = 1.0f / (1.0f + r);
    float w1 = r / (1.0f + r);
    int p0 = atomicAdd(&g_cnt[i0], 1);
    g_tok[i0 * T_TOK + p0] = t; g_wgt[i0 * T_TOK + p0] = w0;
    int p1 = atomicAdd(&g_cnt[i1], 1);
    g_tok[i1 * T_TOK + p1] = t; g_wgt[i1 * T_TOK + p1] = w1;
}

// ---------------------------------------------------------------------------
// fp32 -> fp16 pre-conversion (streaming)
// ---------------------------------------------------------------------------
__global__ void cvt_kernel(const float* __restrict__ src,
                           unsigned* __restrict__ dst, long long npairs) {
    long long i = (long long)blockIdx.x * blockDim.x + threadIdx.x;
    long long stride = (long long)gridDim.x * blockDim.x;
    for (; 2 * i < npairs; i += stride) {
        float4 v = *(const float4*)(src + i * 4);
        *(uint2*)(dst + i * 2) = make_uint2(f16pair(v.x, v.y), f16pair(v.z, v.w));
    }
}

// ---------------------------------------------------------------------------
// Consumer warp-MMA for one K-chunk. Per warp: 64(M) x 64(N), K=32, fp16.
// ---------------------------------------------------------------------------
__device__ __forceinline__ void compute_chunk(
    float acc[4][8][4], uint32_t aB, uint32_t bB)
{
#pragma unroll
    for (int ks = 0; ks < 2; ks++) {
        const uint32_t ko = ks * 32;
        uint32_t b[16];
#pragma unroll
        for (int t = 0; t < 4; t++) ldm4(b + 4 * t, bB + t * 16 * RSTRIDE + ko);
#pragma unroll
        for (int mf = 0; mf < 4; mf++) {
            uint32_t a4[4];
            ldm4(a4, aB + mf * 16 * RSTRIDE + ko);
#pragma unroll
            for (int nf = 0; nf < 8; nf++)
                mma_f16(acc[mf][nf], a4, b[2 * nf], b[2 * nf + 1]);
        }
    }
}

// Producer: cp.async one chunk. A: 2 rows x 4 x 16B, B: 4 rows x 4 x 16B.
__device__ __forceinline__ void produce_chunk(
    uint32_t stg, int c,
    const unsigned* a0p, const unsigned* a1p, uint32_t a0s, uint32_t a1s,
    const unsigned* const* bpp, uint32_t b0s)
{
    const unsigned* s0 = a0p + c * 16;
    const unsigned* s1 = a1p + c * 16;
#pragma unroll
    for (int j = 0; j < 4; j++) cpa16(stg + a0s + j * 16, s0 + j * 4);
#pragma unroll
    for (int j = 0; j < 4; j++) cpa16(stg + a1s + j * 16, s1 + j * 4);
    const uint32_t bb = stg + A_BYTES + b0s;
#pragma unroll
    for (int q = 0; q < 4; q++) {
        const unsigned* bs = bpp[q] + c * 16;
#pragma unroll
        for (int j = 0; j < 4; j++)
            cpa16(bb + (uint32_t)q * RSTRIDE + j * 16, bs + j * 4);
    }
}

// ---------------------------------------------------------------------------
// GEMM1: [128 gathered tokens] x [128 gate + 128 up cols], K=2048
//   grid = (64, 11, 8), 320 threads (8 consumer + 2 producer warps)
// ---------------------------------------------------------------------------
__global__ __launch_bounds__(NTHREADS, 1)
void gemm1_mma(const float* __restrict__ hidden, const float* __restrict__ w1) {
    const int e   = blockIdx.z;
    const int cnt = g_cnt[e];
    const int m0  = blockIdx.x * 128;
    if (m0 >= cnt) return;
    const int n0t = blockIdx.y * 128;

    extern __shared__ char smem[];
    const uint32_t sbase = smem_u32(smem);
    int* stok = (int*)smem;
    const uint32_t tiles = sbase + SMEM_TILES_OFF;

    const int tid  = threadIdx.x;
    const int lane = tid & 31;
    const int wid  = tid >> 5;
    const bool is_prod = (wid >= 8);

    if (tid < 128) {
        int i = m0 + tid;
        stok[tid] = (i < cnt) ? g_tok[e * T_TOK + i] : 0;
    }
    __syncthreads();

    // ---- producer setup ----
    const unsigned *pa0 = 0, *pa1 = 0;
    const unsigned* pb[4] = {0, 0, 0, 0};
    uint32_t a0s = 0, a1s = 0, b0s = 0;
    if (is_prod) {
        const int pt = tid - 256;              // 0..63
        const int ra = pt * 2;
        pa0 = g_hid16 + (size_t)stok[ra] * HH;
        pa1 = g_hid16 + (size_t)stok[ra + 1] * HH;
        a0s = (uint32_t)(ra * RSTRIDE);
        a1s = (uint32_t)((ra + 1) * RSTRIDE);
        const unsigned* w1e = g_w1_16 + (size_t)e * F2 * HH;
#pragma unroll
        for (int q = 0; q < 4; q++) {
            const int rb = pt * 4 + q;
            const int bj = (rb >> 3) & 7;
            const int fcol = n0t + (rb >> 6) * 32 + ((bj >> 1) * 8) + (rb & 7);
            const int grow = fcol + ((bj & 1) ? F_DIM : 0);
            pb[q] = w1e + (size_t)grow * HH;
        }
        b0s = (uint32_t)((pt * 4) * RSTRIDE);
        // prologue: chunks 0 and 1
        produce_chunk(tiles, 0, pa0, pa1, a0s, a1s, pb, b0s); CP_COMMIT();
        produce_chunk(tiles + STAGE_B, 1, pa0, pa1, a0s, a1s, pb, b0s); CP_COMMIT();
        CP_WAIT1();   // chunk 0 complete
    }

    // ---- consumer setup ----
    const int wrow = wid & 1;
    const int wcol = wid >> 1;
    const uint32_t a_loff = (uint32_t)((lane & 15) * RSTRIDE + (lane >> 4) * 16)
                          + (uint32_t)(wrow * 64) * RSTRIDE;
    const uint32_t b_loff = (uint32_t)(((lane & 7) + ((lane >> 4) & 1) * 8) * RSTRIDE
                                       + ((lane >> 3) & 1) * 16)
                          + (uint32_t)(wcol * 64) * RSTRIDE;

    float acc[4][8][4];
#pragma unroll
    for (int i = 0; i < 4; i++)
#pragma unroll
        for (int j = 0; j < 8; j++)
#pragma unroll
            for (int q = 0; q < 4; q++) acc[i][j][q] = 0.0f;

    __syncthreads();

    const int NC = H_DIM / BK;   // 64
    for (int c = 0; c < NC; c++) {
        if (is_prod) {
            if (c + 2 < NC)
                produce_chunk(tiles + (uint32_t)((c + 2) % 3) * STAGE_B, c + 2,
                              pa0, pa1, a0s, a1s, pb, b0s);
            CP_COMMIT();
            CP_WAIT1();   // chunk c+1 complete before next iteration
        } else {
            const uint32_t rb = tiles + (uint32_t)(c % 3) * STAGE_B;
            compute_chunk(acc, rb + a_loff, rb + A_BYTES + b_loff);
        }
        __syncthreads();
    }

    if (is_prod) return;

    // epilogue: silu(gate)*up -> g_act fp16 pairs (gate=even nf, up=odd nf)
    const int g   = lane >> 2;
    const int tig = lane & 3;
#pragma unroll
    for (int mf = 0; mf < 4; mf++) {
        const int r0 = wrow * 64 + mf * 16 + g;
        const int r1 = r0 + 8;
#pragma unroll
        for (int p = 0; p < 4; p++) {
            const int ci = ((n0t + wcol * 32 + p * 8) >> 1) + tig;
            if (m0 + r0 < cnt) {
                float g0 = acc[mf][2*p][0],   g1v = acc[mf][2*p][1];
                float u0 = acc[mf][2*p+1][0], u1  = acc[mf][2*p+1][1];
                float a0 = (g0 / (1.0f + expf(-g0))) * u0;
                float a1 = (g1v / (1.0f + expf(-g1v))) * u1;
                g_act[(size_t)(e * T_TOK + m0 + r0) * FH + ci] = f16pair(a0, a1);
            }
            if (m0 + r1 < cnt) {
                float g0 = acc[mf][2*p][2],   g1v = acc[mf][2*p][3];
                float u0 = acc[mf][2*p+1][2], u1  = acc[mf][2*p+1][3];
                float a0 = (g0 / (1.0f + expf(-g0))) * u0;
                float a1 = (g1v / (1.0f + expf(-g1v))) * u1;
                g_act[(size_t)(e * T_TOK + m0 + r1) * FH + ci] = f16pair(a0, a1);
            }
        }
    }
}

// ---------------------------------------------------------------------------
// GEMM2: [128 slots] x [256 H cols], K=1408; weighted atomic scatter into out
//   grid = (64, 8, 8), 320 threads
// ---------------------------------------------------------------------------
__global__ __launch_bounds__(NTHREADS, 1)
void gemm2_mma(float* __restrict__ out) {
    const int e   = blockIdx.z;
    const int cnt = g_cnt[e];
    const int m0  = blockIdx.x * 128;
    if (m0 >= cnt) return;
    const int n0  = blockIdx.y * 256;

    extern __shared__ char smem[];
    const uint32_t sbase = smem_u32(smem);
    int* stok = (int*)smem;
    const uint32_t tiles = sbase + SMEM_TILES_OFF;

    const int tid  = threadIdx.x;
    const int lane = tid & 31;
    const int wid  = tid >> 5;
    const bool is_prod = (wid >= 8);

    if (tid < 128) {
        int i = m0 + tid;
        stok[tid] = (i < cnt) ? g_tok[e * T_TOK + i] : 0;
    }
    __syncthreads();

    // ---- producer setup ----
    const unsigned *pa0 = 0, *pa1 = 0;
    const unsigned* pb[4] = {0, 0, 0, 0};
    uint32_t a0s = 0, a1s = 0, b0s = 0;
    if (is_prod) {
        const int pt = tid - 256;
        const int ra = pt * 2;
        pa0 = g_act + (size_t)(e * T_TOK + m0 + ra) * FH;
        pa1 = g_act + (size_t)(e * T_TOK + m0 + ra + 1) * FH;
        a0s = (uint32_t)(ra * RSTRIDE);
        a1s = (uint32_t)((ra + 1) * RSTRIDE);
        const unsigned* w2e = g_w2_16 + (size_t)e * H_DIM * FH;
#pragma unroll
        for (int q = 0; q < 4; q++)
            pb[q] = w2e + (size_t)(n0 + pt * 4 + q) * FH;
        b0s = (uint32_t)((pt * 4) * RSTRIDE);
        produce_chunk(tiles, 0, pa0, pa1, a0s, a1s, pb, b0s); CP_COMMIT();
        produce_chunk(tiles + STAGE_B, 1, pa0, pa1, a0s, a1s, pb, b0s); CP_COMMIT();
        CP_WAIT1();
    }

    const int wrow = wid & 1;
    const int wcol = wid >> 1;
    const uint32_t a_loff = (uint32_t)((lane & 15) * RSTRIDE + (lane >> 4) * 16)
                          + (uint32_t)(wrow * 64) * RSTRIDE;
    const uint32_t b_loff = (uint32_t)(((lane & 7) + ((lane >> 4) & 1) * 8) * RSTRIDE
                                       + ((lane >> 3) & 1) * 16)
                          + (uint32_t)(wcol * 64) * RSTRIDE;

    float acc[4][8][4];
#pragma unroll
    for (int i = 0; i < 4; i++)
#pragma unroll
        for (int j = 0; j < 8; j++)
#pragma unroll
            for (int q = 0; q < 4; q++) acc[i][j][q] = 0.0f;

    __syncthreads();

    const int NC = F_DIM / BK;   // 44
    for (int c = 0; c < NC; c++) {
        if (is_prod) {
            if (c + 2 < NC)
                produce_chunk(tiles + (uint32_t)((c + 2) % 3) * STAGE_B, c + 2,
                              pa0, pa1, a0s, a1s, pb, b0s);
            CP_COMMIT();
            CP_WAIT1();
        } else {
            const uint32_t rb = tiles + (uint32_t)(c % 3) * STAGE_B;
            compute_chunk(acc, rb + a_loff, rb + A_BYTES + b_loff);
        }
        __syncthreads();
    }

    if (is_prod) return;

    // epilogue: out[token] += w * y (exactly 2 atomics per element across grid)
    const int g   = lane >> 2;
    const int tig = lane & 3;
#pragma unroll
    for (int mf = 0; mf < 4; mf++) {
        const int r0 = wrow * 64 + mf * 16 + g;
        const int r1 = r0 + 8;
        const bool v0 = (m0 + r0) < cnt;
        const bool v1 = (m0 + r1) < cnt;
        const float w0 = v0 ? g_wgt[e * T_TOK + m0 + r0] : 0.0f;
        const float w1 = v1 ? g_wgt[e * T_TOK + m0 + r1] : 0.0f;
        float* o0 = out + (size_t)stok[r0] * H_DIM;
        float* o1 = out + (size_t)stok[r1] * H_DIM;
#pragma unroll
        for (int nf = 0; nf < 8; nf++) {
            const int col = n0 + wcol * 64 + nf * 8 + 2 * tig;
            if (v0) {
                atomicAdd(o0 + col,     w0 * acc[mf][nf][0]);
                atomicAdd(o0 + col + 1, w0 * acc[mf][nf][1]);
            }
            if (v1) {
                atomicAdd(o1 + col,     w1 * acc[mf][nf][2]);
                atomicAdd(o1 + col + 1, w1 * acc[mf][nf][3]);
            }
        }
    }
}

// ---------------------------------------------------------------------------
// Launch
// ---------------------------------------------------------------------------
extern "C" void kernel_launch(void* const* d_in, const int* in_sizes, int n_in,
                              void* d_out, int out_size) {
    (void)in_sizes; (void)n_in; (void)out_size;
    const float* hidden = (const float*)d_in[0];
    const float* logits = (const float*)d_in[1];
    const float* w1     = (const float*)d_in[2];
    const float* w2     = (const float*)d_in[3];
    float*       out    = (float*)d_out;

    cudaFuncSetAttribute(gemm1_mma, cudaFuncAttributeMaxDynamicSharedMemorySize, SMEM_TOTAL);
    cudaFuncSetAttribute(gemm2_mma, cudaFuncAttributeMaxDynamicSharedMemorySize, SMEM_TOTAL);

    unsigned *hh, *w1h, *w2h;
    cudaGetSymbolAddress((void**)&hh,  g_hid16);
    cudaGetSymbolAddress((void**)&w1h, g_w1_16);
    cudaGetSymbolAddress((void**)&w2h, g_w2_16);

    init_kernel<<<2048, 256>>>(out);
    route_kernel<<<T_TOK / 256, 256>>>(logits);

    cvt_kernel<<<4096, 256>>>(hidden, hh,  HID_PAIRS);
    cvt_kernel<<<8192, 256>>>(w1,     w1h, W1_PAIRS);
    cvt_kernel<<<8192, 256>>>(w2,     w2h, W2_PAIRS);

    dim3 g1(T_TOK / 128, F_DIM / 128, E_NUM);   // (64, 11, 8)
    gemm1_mma<<<g1, NTHREADS, SMEM_TOTAL>>>(hidden, w1);

    dim3 g2(T_TOK / 128, H_DIM / 256, E_NUM);   // (64, 8, 8)
    gemm2_mma<<<g2, NTHREADS, SMEM_TOTAL>>>(out);
}